// round 13
// baseline (speedup 1.0000x reference)
#include <cuda_runtime.h>
#include <cstdint>

#define COLS 8192
#define COLS4 2048
#define ROWS 1024
#define SCALE 0.75f
#define HALF 4096
#define GRID 148
#define NTHR 512
#define P1_ITEMS 8192          // 2048 col4 x 4 octets
#define P1_PER_BLK 56          // ceil(8192/148)

// Scratch + barrier state (no allocation allowed). Zero-initialized.
__device__ __align__(32) float g_wtotal[COLS];
__device__ unsigned g_count;
__device__ unsigned g_epoch;

// LDG.256 + evict_last (x stream: L2-resident across graph replays).
__device__ __forceinline__ void ldg256_el(const float* p, float4& a, float4& b) {
    unsigned r0, r1, r2, r3, r4, r5, r6, r7;
    asm volatile("ld.global.nc.L2::evict_last.v8.b32 {%0,%1,%2,%3,%4,%5,%6,%7}, [%8];"
        : "=r"(r0), "=r"(r1), "=r"(r2), "=r"(r3),
          "=r"(r4), "=r"(r5), "=r"(r6), "=r"(r7)
        : "l"(p));
    a.x = __uint_as_float(r0); a.y = __uint_as_float(r1);
    a.z = __uint_as_float(r2); a.w = __uint_as_float(r3);
    b.x = __uint_as_float(r4); b.y = __uint_as_float(r5);
    b.z = __uint_as_float(r6); b.w = __uint_as_float(r7);
}
// Plain LDG.256 (w: L1/L2-hot).
__device__ __forceinline__ void ldg256(const float* p, float4& a, float4& b) {
    unsigned r0, r1, r2, r3, r4, r5, r6, r7;
    asm volatile("ld.global.nc.v8.b32 {%0,%1,%2,%3,%4,%5,%6,%7}, [%8];"
        : "=r"(r0), "=r"(r1), "=r"(r2), "=r"(r3),
          "=r"(r4), "=r"(r5), "=r"(r6), "=r"(r7)
        : "l"(p));
    a.x = __uint_as_float(r0); a.y = __uint_as_float(r1);
    a.z = __uint_as_float(r2); a.w = __uint_as_float(r3);
    b.x = __uint_as_float(r4); b.y = __uint_as_float(r5);
    b.z = __uint_as_float(r6); b.w = __uint_as_float(r7);
}

// Fused kernel: phase 1 (w reduce, 64 threads/block) + grid barrier +
// phase 2 (R9-shape dot: warp per half-row, 16-iter stream). x prefetch for
// iterations 0-1 is issued BEFORE the barrier to overlap phase 1.
__global__ __launch_bounds__(NTHR, 1) void fused_kernel(const float* __restrict__ x,
                                                        const float* __restrict__ wsums,
                                                        float* __restrict__ out) {
    const int t   = threadIdx.x;
    const int bid = blockIdx.x;
    const int wid = t >> 5;
    const int lid = t & 31;

    // ---- Phase-2 geometry (computed early for prefetch) ----
    const int k    = wid >> 1;                  // 0..7
    const int row  = k * GRID + bid;            // row this warp-pair serves
    const int half = wid & 1;
    const bool rvalid = (row < ROWS) && (k < 7);

    const float* __restrict__ xr = x + (size_t)row * COLS + half * HALF + lid * 8;
    const float* __restrict__ wr = g_wtotal + half * HALF + lid * 8;

    // Prefetch x iterations 0,1 (independent of w) before phase 1 / barrier.
    float4 pa[2][2];
    if (rvalid) {
        ldg256_el(xr + 0 * 256, pa[0][0], pa[0][1]);
        ldg256_el(xr + 1 * 256, pa[1][0], pa[1][1]);
    }

    // ---- Phase 1: w_total = sum_g wsums[g][:] ----
    // 64 threads/block; item = bid*56 + t, item = (col4<<2)|oct; each thread
    // sums 8 groups of its octet, 4 octet lanes shuffle-combine, lane oct==0 writes.
    if (t < 64) {
        const int item  = bid * P1_PER_BLK + t;
        const bool valid = (t < P1_PER_BLK) && (item < P1_ITEMS);
        const int col4 = valid ? (item >> 2) : 0;
        const int oct  = item & 3;

        const float4* __restrict__ w4 = reinterpret_cast<const float4*>(wsums);
        float4 s = make_float4(0.f, 0.f, 0.f, 0.f);
#pragma unroll
        for (int g = 0; g < 8; ++g) {
            float4 v = w4[(size_t)(oct * 8 + g) * COLS4 + col4];
            s.x += v.x; s.y += v.y; s.z += v.z; s.w += v.w;
        }
        if (!valid) { s.x = s.y = s.z = s.w = 0.f; }
#pragma unroll
        for (int o = 1; o <= 2; o <<= 1) {
            s.x += __shfl_xor_sync(0xFFFFFFFFu, s.x, o);
            s.y += __shfl_xor_sync(0xFFFFFFFFu, s.y, o);
            s.z += __shfl_xor_sync(0xFFFFFFFFu, s.z, o);
            s.w += __shfl_xor_sync(0xFFFFFFFFu, s.w, o);
        }
        if (valid && oct == 0)
            reinterpret_cast<float4*>(g_wtotal)[col4] = s;
        __threadfence();
    }
    __syncthreads();

    // ---- Grid barrier (all 148 blocks are wave-1 resident) ----
    if (t == 0) {
        const unsigned e = atomicAdd(&g_epoch, 0u);
        if (atomicAdd(&g_count, 1u) == GRID - 1) {
            g_count = 0;
            __threadfence();
            atomicAdd(&g_epoch, 1u);
        } else {
            while (atomicAdd(&g_epoch, 0u) == e) { }
        }
    }
    __syncthreads();

    // ---- Phase 2: 16-iteration half-row dot (R9 body, 2-ahead rotation) ----
    float u = 0.f;
    if (rvalid) {
        float p0 = 0.f, p1 = 0.f, p2 = 0.f, p3 = 0.f;
#pragma unroll
        for (int i = 0; i < 16; ++i) {
            const int slot = i & 1;
            float4 w0, w1;
            ldg256(wr + i * 256, w0, w1);
            const float4 a0 = pa[slot][0], a1 = pa[slot][1];
            if (i + 2 < 16)
                ldg256_el(xr + (i + 2) * 256, pa[slot][0], pa[slot][1]);
            p0 = fmaf(a0.x, w0.x, p0); p1 = fmaf(a0.y, w0.y, p1);
            p2 = fmaf(a0.z, w0.z, p2); p3 = fmaf(a0.w, w0.w, p3);
            p0 = fmaf(a1.x, w1.x, p0); p1 = fmaf(a1.y, w1.y, p1);
            p2 = fmaf(a1.z, w1.z, p2); p3 = fmaf(a1.w, w1.w, p3);
        }
        u = (p0 + p1) + (p2 + p3);
    }

#pragma unroll
    for (int o = 16; o > 0; o >>= 1)
        u += __shfl_xor_sync(0xFFFFFFFFu, u, o);

    __shared__ float red[7][2];
    if (lid == 0 && rvalid) red[k][half] = u;
    __syncthreads();

    if (t < 7) {
        const int r = t * GRID + bid;
        if (r < ROWS)
            out[r] = SCALE * (red[t][0] + red[t][1]);
    }
}

extern "C" void kernel_launch(void* const* d_in, const int* in_sizes, int n_in,
                              void* d_out, int out_size) {
    const float* x     = (const float*)d_in[0];  // [1024, 8192] f32
    const float* wsums = (const float*)d_in[1];  // [32, 8192] f32
    float* out         = (float*)d_out;          // [1024, 1] f32

    fused_kernel<<<GRID, NTHR>>>(x, wsums, out);
}